// round 1
// baseline (speedup 1.0000x reference)
#include <cuda_runtime.h>

#define BB 2
#define SS 2048
#define DM 4096
#define NH 32
#define HD 128
#define QL 12
#define KL 4
#define NT (BB*SS)   // 4096 tokens

// ---------------- scratch (device globals; no allocations) ----------------
__device__ __align__(16) float g_Ckv[NT*KL];        // 64 KB
__device__ __align__(16) float g_q  [NT*NH*KL];     // 2 MB  (pre-scaled by 0.5)
__device__ __align__(16) float g_A  [NT*NH*KL];     // 2 MB  (attended latent)
__device__ __align__(16) float g_M  [NH*KL*DM];     // 2 MB  (Wv_u folded into Wo)
__device__ __align__(16) float g_Mb [NH*DM];        // 512 KB (per-head bias partials)
__device__ __align__(16) float g_bo [DM];           // effective output bias

// ============ Kernel 1: x -> C_q, C_kv, q (fused low-rank projections) =====
// grid 128 blocks x 32 tokens, 512 threads. Thread = (token, one of 16 outs).
__global__ __launch_bounds__(512) void proj_kernel(
    const float* __restrict__ x,   const float* __restrict__ Wq,
    const float* __restrict__ bq,  const float* __restrict__ Wqk,
    const float* __restrict__ bqk, const float* __restrict__ Wkv,
    const float* __restrict__ bkv)
{
    __shared__ __align__(16) float xs[32][128];
    __shared__ __align__(16) float ws[16][132];   // pad 132 -> 2-way max conflict
    __shared__ float cq[32][16];

    const int tid  = threadIdx.x;
    const int tok0 = blockIdx.x * 32;
    const int tok  = tid >> 4;
    const int c    = tid & 15;

    float acc = 0.f;
    for (int d0 = 0; d0 < DM; d0 += 128) {
        #pragma unroll
        for (int i = tid; i < 32*128; i += 512) {
            int t = i >> 7, d = i & 127;
            xs[t][d] = x[(size_t)(tok0 + t)*DM + d0 + d];
        }
        #pragma unroll
        for (int i = tid; i < 16*128; i += 512) {
            int d = i >> 4, cc = i & 15;
            ws[cc][d] = (cc < QL) ? Wq[(size_t)(d0+d)*QL + cc]
                                  : Wkv[(size_t)(d0+d)*KL + (cc-QL)];
        }
        __syncthreads();
        #pragma unroll 8
        for (int d = 0; d < 128; d += 4) {
            float4 xv = *(const float4*)&xs[tok][d];
            float4 wv = *(const float4*)&ws[c][d];
            acc = fmaf(xv.x, wv.x, acc);
            acc = fmaf(xv.y, wv.y, acc);
            acc = fmaf(xv.z, wv.z, acc);
            acc = fmaf(xv.w, wv.w, acc);
        }
        __syncthreads();
    }
    float biased = acc + ((c < QL) ? bq[c] : bkv[c - QL]);
    cq[tok][c] = biased;
    if (c >= QL) g_Ckv[(size_t)(tok0 + tok)*KL + (c - QL)] = biased;
    __syncthreads();

    // q = 0.5 * (C_q @ W_qk + b_qk)   (0.5 = 1/sqrt(KV_LAT))
    float cql[QL];
    #pragma unroll
    for (int i = 0; i < QL; ++i) cql[i] = cq[tok][i];
    const int o0 = c * 8;
    #pragma unroll
    for (int oo = 0; oo < 8; ++oo) {
        int o = o0 + oo;
        float s = bqk[o];
        #pragma unroll
        for (int i = 0; i < QL; ++i) s = fmaf(cql[i], Wqk[i*(NH*KL) + o], s);
        g_q[(size_t)(tok0 + tok)*(NH*KL) + o] = 0.5f * s;
    }
}

// ============ Kernel 2: M[h*4+l, j] = sum_d Wv_u[l, h*128+d] * Wo[h*128+d, j]
// grid (16 j-tiles, 32 heads), 256 threads. Reads Wo exactly once.
__global__ __launch_bounds__(256) void precM_kernel(
    const float* __restrict__ Wvu, const float* __restrict__ Wo,
    const float* __restrict__ bvu)
{
    __shared__ float vu[KL][HD];
    __shared__ float bvs[HD];
    const int h = blockIdx.y;
    const int j = blockIdx.x * 256 + threadIdx.x;
    for (int i = threadIdx.x; i < KL*HD; i += 256) {
        int k = i >> 7, d = i & 127;
        vu[k][d] = Wvu[(size_t)k*(NH*HD) + h*HD + d];
    }
    if (threadIdx.x < HD) bvs[threadIdx.x] = bvu[h*HD + threadIdx.x];
    __syncthreads();

    float a0=0.f, a1=0.f, a2=0.f, a3=0.f, ab=0.f;
    #pragma unroll 4
    for (int d = 0; d < HD; ++d) {
        float w = Wo[(size_t)(h*HD + d)*DM + j];
        a0 = fmaf(vu[0][d], w, a0);
        a1 = fmaf(vu[1][d], w, a1);
        a2 = fmaf(vu[2][d], w, a2);
        a3 = fmaf(vu[3][d], w, a3);
        ab = fmaf(bvs[d],   w, ab);
    }
    g_M[(size_t)(h*KL + 0)*DM + j] = a0;
    g_M[(size_t)(h*KL + 1)*DM + j] = a1;
    g_M[(size_t)(h*KL + 2)*DM + j] = a2;
    g_M[(size_t)(h*KL + 3)*DM + j] = a3;
    g_Mb[(size_t)h*DM + j] = ab;
}

// ============ Kernel 2c: bo_eff = bo + sum_h Mb[h] ==========================
__global__ __launch_bounds__(256) void biascomb_kernel(const float* __restrict__ bo)
{
    int j = blockIdx.x * 256 + threadIdx.x;
    float acc = bo[j];
    #pragma unroll
    for (int h = 0; h < NH; ++h) acc += g_Mb[(size_t)h*DM + j];
    g_bo[j] = acc;
}

// ============ Kernel 3: streaming latent attention ==========================
// grid (8 q-tiles, 32 heads, 2 batch), 256 threads; 1 thread = 1 query row.
// C_kv[b] (2048x4 = 32 KB) lives in SMEM; every lane reads the same k (broadcast).
__global__ __launch_bounds__(256) void attn_kernel()
{
    __shared__ __align__(16) float4 ck[SS];
    const int b = blockIdx.z, h = blockIdx.y;
    const float4* ckv = (const float4*)(g_Ckv + (size_t)b*SS*KL);
    for (int i = threadIdx.x; i < SS; i += 256) ck[i] = ckv[i];
    __syncthreads();

    const int tok = b*SS + blockIdx.x*256 + threadIdx.x;
    const float4 qv = *(const float4*)(g_q + (size_t)tok*(NH*KL) + h*KL);

    float l = 0.f, a0 = 0.f, a1 = 0.f, a2 = 0.f, a3 = 0.f;
    #pragma unroll 4
    for (int k = 0; k < SS; ++k) {
        float4 c = ck[k];
        float s = qv.x*c.x;
        s = fmaf(qv.y, c.y, s);
        s = fmaf(qv.z, c.z, s);
        s = fmaf(qv.w, c.w, s);
        float e = __expf(s);        // no-max softmax: |s| <~ 30, fp32 safe
        l += e;
        a0 = fmaf(e, c.x, a0);
        a1 = fmaf(e, c.y, a1);
        a2 = fmaf(e, c.z, a2);
        a3 = fmaf(e, c.w, a3);
    }
    float inv = 1.f / l;
    float4 r; r.x = a0*inv; r.y = a1*inv; r.z = a2*inv; r.w = a3*inv;
    *(float4*)(g_A + (size_t)tok*(NH*KL) + h*KL) = r;
}

// ============ Kernel 4: out = Acat[4096,128] @ M[128,4096] + bo_eff =========
// 64x64 tile per block, 4x4 microtile per thread, K chunked 2x64.
__global__ __launch_bounds__(256) void final_kernel(float* __restrict__ out)
{
    __shared__ __align__(16) float As[64][64];
    __shared__ __align__(16) float Bs[64][64];
    const int tok0 = blockIdx.y * 64, j0 = blockIdx.x * 64;
    const int tx = threadIdx.x & 15, ty = threadIdx.x >> 4;

    float acc[4][4] = {};
    for (int k0 = 0; k0 < NH*KL; k0 += 64) {
        #pragma unroll
        for (int i = threadIdx.x; i < 64*64; i += 256) {
            int r = i >> 6, cc = i & 63;
            As[r][cc] = g_A[(size_t)(tok0 + r)*(NH*KL) + k0 + cc];
            Bs[r][cc] = g_M[(size_t)(k0 + r)*DM + j0 + cc];
        }
        __syncthreads();
        #pragma unroll
        for (int k = 0; k < 64; ++k) {
            float a0 = As[ty*4+0][k], a1 = As[ty*4+1][k];
            float a2 = As[ty*4+2][k], a3 = As[ty*4+3][k];
            float4 bv = *(const float4*)&Bs[k][tx*4];
            acc[0][0]=fmaf(a0,bv.x,acc[0][0]); acc[0][1]=fmaf(a0,bv.y,acc[0][1]);
            acc[0][2]=fmaf(a0,bv.z,acc[0][2]); acc[0][3]=fmaf(a0,bv.w,acc[0][3]);
            acc[1][0]=fmaf(a1,bv.x,acc[1][0]); acc[1][1]=fmaf(a1,bv.y,acc[1][1]);
            acc[1][2]=fmaf(a1,bv.z,acc[1][2]); acc[1][3]=fmaf(a1,bv.w,acc[1][3]);
            acc[2][0]=fmaf(a2,bv.x,acc[2][0]); acc[2][1]=fmaf(a2,bv.y,acc[2][1]);
            acc[2][2]=fmaf(a2,bv.z,acc[2][2]); acc[2][3]=fmaf(a2,bv.w,acc[2][3]);
            acc[3][0]=fmaf(a3,bv.x,acc[3][0]); acc[3][1]=fmaf(a3,bv.y,acc[3][1]);
            acc[3][2]=fmaf(a3,bv.z,acc[3][2]); acc[3][3]=fmaf(a3,bv.w,acc[3][3]);
        }
        __syncthreads();
    }
    const float4 bj = *(const float4*)&g_bo[j0 + tx*4];
    #pragma unroll
    for (int i = 0; i < 4; ++i) {
        float4 r;
        r.x = acc[i][0] + bj.x; r.y = acc[i][1] + bj.y;
        r.z = acc[i][2] + bj.z; r.w = acc[i][3] + bj.w;
        *(float4*)&out[(size_t)(tok0 + ty*4 + i)*DM + j0 + tx*4] = r;
    }
}

// ============================================================================
extern "C" void kernel_launch(void* const* d_in, const int* in_sizes, int n_in,
                              void* d_out, int out_size)
{
    const float* x    = (const float*)d_in[0];
    const float* Wq_d = (const float*)d_in[1];
    const float* bq_d = (const float*)d_in[2];
    const float* W_qk = (const float*)d_in[3];
    const float* b_qk = (const float*)d_in[4];
    const float* Wkv_d= (const float*)d_in[5];
    const float* bkv_d= (const float*)d_in[6];
    const float* Wv_u = (const float*)d_in[7];
    const float* bv_u = (const float*)d_in[8];
    const float* Wo   = (const float*)d_in[9];
    const float* bo   = (const float*)d_in[10];
    float* out = (float*)d_out;

    proj_kernel<<<NT/32, 512>>>(x, Wq_d, bq_d, W_qk, b_qk, Wkv_d, bkv_d);
    precM_kernel<<<dim3(DM/256, NH), 256>>>(Wv_u, Wo, bv_u);
    biascomb_kernel<<<DM/256, 256>>>(bo);
    attn_kernel<<<dim3(SS/256, NH, BB), 256>>>();
    final_kernel<<<dim3(DM/64, NT/64), 256>>>(out);
}

// round 2
// speedup vs baseline: 1.2303x; 1.2303x over previous
#include <cuda_runtime.h>

#define BB 2
#define SS 2048
#define DM 4096
#define NH 32
#define HD 128
#define QL 12
#define KL 4
#define NT (BB*SS)   // 4096 tokens

typedef unsigned long long u64;

// ---------------- f32x2 packed-math helpers (FFMA2 path, sm_103a) ----------
__device__ __forceinline__ u64 f2pack(float lo, float hi) {
    u64 r; asm("mov.b64 %0, {%1, %2};" : "=l"(r) : "f"(lo), "f"(hi)); return r;
}
__device__ __forceinline__ void f2unpack(u64 v, float& lo, float& hi) {
    asm("mov.b64 {%0, %1}, %2;" : "=f"(lo), "=f"(hi) : "l"(v));
}
__device__ __forceinline__ u64 f2fma(u64 a, u64 b, u64 c) {
    u64 d; asm("fma.rn.f32x2 %0, %1, %2, %3;" : "=l"(d) : "l"(a), "l"(b), "l"(c)); return d;
}
__device__ __forceinline__ u64 f2mul(u64 a, u64 b) {
    u64 d; asm("mul.rn.f32x2 %0, %1, %2;" : "=l"(d) : "l"(a), "l"(b)); return d;
}
__device__ __forceinline__ u64 f2add(u64 a, u64 b) {
    u64 d; asm("add.rn.f32x2 %0, %1, %2;" : "=l"(d) : "l"(a), "l"(b)); return d;
}
__device__ __forceinline__ float ex2f(float x) {
    float y; asm("ex2.approx.f32 %0, %1;" : "=f"(y) : "f"(x)); return y;
}

// ---------------- scratch (device globals; no allocations) ----------------
__device__ __align__(16) float g_Ckv[NT*KL];        // 64 KB
__device__ __align__(16) float g_q  [NT*NH*KL];     // 2 MB  (pre-scaled by 0.5*log2e)
__device__ __align__(16) float g_A  [NT*NH*KL];     // 2 MB  (attended latent)
__device__ __align__(16) float g_M  [NH*KL*DM];     // 2 MB  (Wv_u folded into Wo)
__device__ __align__(16) float g_Mb [NH*DM];        // 512 KB
__device__ __align__(16) float g_bo [DM];

#define QSCALE 0.7213475204444817f   /* 0.5 * log2(e) */

// ============ Kernel 1: x -> C_q, C_kv, q ===================================
__global__ __launch_bounds__(512) void proj_kernel(
    const float* __restrict__ x,   const float* __restrict__ Wq,
    const float* __restrict__ bq,  const float* __restrict__ Wqk,
    const float* __restrict__ bqk, const float* __restrict__ Wkv,
    const float* __restrict__ bkv)
{
    __shared__ __align__(16) float xs[32][128];
    __shared__ __align__(16) float ws[16][132];
    __shared__ float cq[32][16];

    const int tid  = threadIdx.x;
    const int tok0 = blockIdx.x * 32;
    const int tok  = tid >> 4;
    const int c    = tid & 15;

    u64 acc2 = 0ull;
    for (int d0 = 0; d0 < DM; d0 += 128) {
        #pragma unroll
        for (int i = tid; i < 32*128; i += 512) {
            int t = i >> 7, d = i & 127;
            xs[t][d] = x[(size_t)(tok0 + t)*DM + d0 + d];
        }
        #pragma unroll
        for (int i = tid; i < 16*128; i += 512) {
            int d = i >> 4, cc = i & 15;
            ws[cc][d] = (cc < QL) ? Wq[(size_t)(d0+d)*QL + cc]
                                  : Wkv[(size_t)(d0+d)*KL + (cc-QL)];
        }
        __syncthreads();
        #pragma unroll 8
        for (int d = 0; d < 128; d += 4) {
            ulonglong2 xv = *(const ulonglong2*)&xs[tok][d];
            ulonglong2 wv = *(const ulonglong2*)&ws[c][d];
            acc2 = f2fma(xv.x, wv.x, acc2);
            acc2 = f2fma(xv.y, wv.y, acc2);
        }
        __syncthreads();
    }
    float alo, ahi; f2unpack(acc2, alo, ahi);
    float biased = (alo + ahi) + ((c < QL) ? bq[c] : bkv[c - QL]);
    cq[tok][c] = biased;
    if (c >= QL) g_Ckv[(size_t)(tok0 + tok)*KL + (c - QL)] = biased;
    __syncthreads();

    float cql[QL];
    #pragma unroll
    for (int i = 0; i < QL; ++i) cql[i] = cq[tok][i];
    const int o0 = c * 8;
    #pragma unroll
    for (int oo = 0; oo < 8; ++oo) {
        int o = o0 + oo;
        float s = bqk[o];
        #pragma unroll
        for (int i = 0; i < QL; ++i) s = fmaf(cql[i], Wqk[i*(NH*KL) + o], s);
        g_q[(size_t)(tok0 + tok)*(NH*KL) + o] = QSCALE * s;
    }
}

// ============ Kernel 2: fold Wv_u into Wo ===================================
__global__ __launch_bounds__(256) void precM_kernel(
    const float* __restrict__ Wvu, const float* __restrict__ Wo,
    const float* __restrict__ bvu)
{
    __shared__ float vu[KL][HD];
    __shared__ float bvs[HD];
    const int h = blockIdx.y;
    const int j = blockIdx.x * 256 + threadIdx.x;
    for (int i = threadIdx.x; i < KL*HD; i += 256) {
        int k = i >> 7, d = i & 127;
        vu[k][d] = Wvu[(size_t)k*(NH*HD) + h*HD + d];
    }
    if (threadIdx.x < HD) bvs[threadIdx.x] = bvu[h*HD + threadIdx.x];
    __syncthreads();

    float a0=0.f, a1=0.f, a2=0.f, a3=0.f, ab=0.f;
    #pragma unroll 4
    for (int d = 0; d < HD; ++d) {
        float w = Wo[(size_t)(h*HD + d)*DM + j];
        a0 = fmaf(vu[0][d], w, a0);
        a1 = fmaf(vu[1][d], w, a1);
        a2 = fmaf(vu[2][d], w, a2);
        a3 = fmaf(vu[3][d], w, a3);
        ab = fmaf(bvs[d],   w, ab);
    }
    g_M[(size_t)(h*KL + 0)*DM + j] = a0;
    g_M[(size_t)(h*KL + 1)*DM + j] = a1;
    g_M[(size_t)(h*KL + 2)*DM + j] = a2;
    g_M[(size_t)(h*KL + 3)*DM + j] = a3;
    g_Mb[(size_t)h*DM + j] = ab;
}

__global__ __launch_bounds__(256) void biascomb_kernel(const float* __restrict__ bo)
{
    int j = blockIdx.x * 256 + threadIdx.x;
    float acc = bo[j];
    #pragma unroll
    for (int h = 0; h < NH; ++h) acc += g_Mb[(size_t)h*DM + j];
    g_bo[j] = acc;
}

// ============ Kernel 3: streaming latent attention (f32x2, SoA keys) ========
// grid (8 q-tiles, 32 heads, 2 batch), 256 threads; 1 thread = 1 query row.
// Processes 2 keys/iter with packed math: 9 fma-pipe instrs / 2 keys.
__global__ __launch_bounds__(256) void attn_kernel()
{
    __shared__ __align__(16) float ckx[SS];
    __shared__ __align__(16) float cky[SS];
    __shared__ __align__(16) float ckz[SS];
    __shared__ __align__(16) float ckw[SS];
    const int b = blockIdx.z, h = blockIdx.y;
    const float4* ckv = (const float4*)(g_Ckv + (size_t)b*SS*KL);
    for (int i = threadIdx.x; i < SS; i += 256) {
        float4 v = ckv[i];
        ckx[i] = v.x; cky[i] = v.y; ckz[i] = v.z; ckw[i] = v.w;
    }
    __syncthreads();

    const int tok = b*SS + blockIdx.x*256 + threadIdx.x;
    const float4 qv = *(const float4*)(g_q + (size_t)tok*(NH*KL) + h*KL);
    const u64 qx2 = f2pack(qv.x, qv.x);
    const u64 qy2 = f2pack(qv.y, qv.y);
    const u64 qz2 = f2pack(qv.z, qv.z);
    const u64 qw2 = f2pack(qv.w, qv.w);

    const u64* cxp = (const u64*)ckx;
    const u64* cyp = (const u64*)cky;
    const u64* czp = (const u64*)ckz;
    const u64* cwp = (const u64*)ckw;

    u64 l2 = 0ull, ax2 = 0ull, ay2 = 0ull, az2 = 0ull, aw2 = 0ull;
    #pragma unroll 8
    for (int k = 0; k < SS/2; ++k) {
        u64 cx = cxp[k], cy = cyp[k], cz = czp[k], cw = cwp[k];
        u64 s2 = f2mul(qx2, cx);
        s2 = f2fma(qy2, cy, s2);
        s2 = f2fma(qz2, cz, s2);
        s2 = f2fma(qw2, cw, s2);
        float s0, s1; f2unpack(s2, s0, s1);
        u64 e2 = f2pack(ex2f(s0), ex2f(s1));   // q pre-scaled by 0.5*log2e
        l2  = f2add(l2, e2);
        ax2 = f2fma(e2, cx, ax2);
        ay2 = f2fma(e2, cy, ay2);
        az2 = f2fma(e2, cz, az2);
        aw2 = f2fma(e2, cw, aw2);
    }
    float l0, l1, x0, x1, y0, y1, z0, z1, w0, w1;
    f2unpack(l2, l0, l1);
    f2unpack(ax2, x0, x1); f2unpack(ay2, y0, y1);
    f2unpack(az2, z0, z1); f2unpack(aw2, w0, w1);
    float inv = 1.f / (l0 + l1);
    float4 r;
    r.x = (x0 + x1) * inv; r.y = (y0 + y1) * inv;
    r.z = (z0 + z1) * inv; r.w = (w0 + w1) * inv;
    *(float4*)(g_A + (size_t)tok*(NH*KL) + h*KL) = r;
}

// ============ Kernel 4: out = A[4096,128] @ M[128,4096] + bo  (f32x2) =======
// 128(tok) x 64(j) tile, 256 threads, 8x4 microtile; A transposed in SMEM so
// row-pairs load as LDS.64 -> 16 packed FMA (32 FMA) per thread-k.
__global__ __launch_bounds__(256) void final_kernel(float* __restrict__ out)
{
    __shared__ __align__(16) float Ast[64][130];   // [k][row], pad for STS
    __shared__ __align__(16) float Bs[64][64];     // [k][j]
    const int tok0 = blockIdx.y * 128, j0 = blockIdx.x * 64;
    const int tx = threadIdx.x & 15, ty = threadIdx.x >> 4;
    const int r0 = ty * 8;

    u64 acc[4][4];
    #pragma unroll
    for (int i = 0; i < 4; ++i)
        #pragma unroll
        for (int j = 0; j < 4; ++j) acc[i][j] = 0ull;

    for (int k0 = 0; k0 < NH*KL; k0 += 64) {
        #pragma unroll
        for (int i = threadIdx.x; i < 128*64; i += 256) {
            int r = i >> 6, k = i & 63;
            Ast[k][r] = g_A[(size_t)(tok0 + r)*(NH*KL) + k0 + k];
        }
        #pragma unroll
        for (int i = threadIdx.x; i < 64*64; i += 256) {
            int r = i >> 6, c = i & 63;
            Bs[r][c] = g_M[(size_t)(k0 + r)*DM + j0 + c];
        }
        __syncthreads();
        #pragma unroll 4
        for (int k = 0; k < 64; ++k) {
            float4 bv = *(const float4*)&Bs[k][tx*4];
            u64 b0 = f2pack(bv.x, bv.x);
            u64 b1 = f2pack(bv.y, bv.y);
            u64 b2 = f2pack(bv.z, bv.z);
            u64 b3 = f2pack(bv.w, bv.w);
            u64 a01 = *(const u64*)&Ast[k][r0 + 0];
            u64 a23 = *(const u64*)&Ast[k][r0 + 2];
            u64 a45 = *(const u64*)&Ast[k][r0 + 4];
            u64 a67 = *(const u64*)&Ast[k][r0 + 6];
            acc[0][0] = f2fma(a01, b0, acc[0][0]);
            acc[0][1] = f2fma(a01, b1, acc[0][1]);
            acc[0][2] = f2fma(a01, b2, acc[0][2]);
            acc[0][3] = f2fma(a01, b3, acc[0][3]);
            acc[1][0] = f2fma(a23, b0, acc[1][0]);
            acc[1][1] = f2fma(a23, b1, acc[1][1]);
            acc[1][2] = f2fma(a23, b2, acc[1][2]);
            acc[1][3] = f2fma(a23, b3, acc[1][3]);
            acc[2][0] = f2fma(a45, b0, acc[2][0]);
            acc[2][1] = f2fma(a45, b1, acc[2][1]);
            acc[2][2] = f2fma(a45, b2, acc[2][2]);
            acc[2][3] = f2fma(a45, b3, acc[2][3]);
            acc[3][0] = f2fma(a67, b0, acc[3][0]);
            acc[3][1] = f2fma(a67, b1, acc[3][1]);
            acc[3][2] = f2fma(a67, b2, acc[3][2]);
            acc[3][3] = f2fma(a67, b3, acc[3][3]);
        }
        __syncthreads();
    }

    const float4 bj = *(const float4*)&g_bo[j0 + tx*4];
    #pragma unroll
    for (int i = 0; i < 4; ++i) {
        float lo0, hi0, lo1, hi1, lo2, hi2, lo3, hi3;
        f2unpack(acc[i][0], lo0, hi0);
        f2unpack(acc[i][1], lo1, hi1);
        f2unpack(acc[i][2], lo2, hi2);
        f2unpack(acc[i][3], lo3, hi3);
        float4 ra, rb;
        ra.x = lo0 + bj.x; ra.y = lo1 + bj.y; ra.z = lo2 + bj.z; ra.w = lo3 + bj.w;
        rb.x = hi0 + bj.x; rb.y = hi1 + bj.y; rb.z = hi2 + bj.z; rb.w = hi3 + bj.w;
        size_t row = (size_t)(tok0 + r0 + 2*i);
        *(float4*)&out[row*DM + j0 + tx*4]       = ra;
        *(float4*)&out[(row + 1)*DM + j0 + tx*4] = rb;
    }
}

// ============================================================================
extern "C" void kernel_launch(void* const* d_in, const int* in_sizes, int n_in,
                              void* d_out, int out_size)
{
    const float* x    = (const float*)d_in[0];
    const float* Wq_d = (const float*)d_in[1];
    const float* bq_d = (const float*)d_in[2];
    const float* W_qk = (const float*)d_in[3];
    const float* b_qk = (const float*)d_in[4];
    const float* Wkv_d= (const float*)d_in[5];
    const float* bkv_d= (const float*)d_in[6];
    const float* Wv_u = (const float*)d_in[7];
    const float* bv_u = (const float*)d_in[8];
    const float* Wo   = (const float*)d_in[9];
    const float* bo   = (const float*)d_in[10];
    float* out = (float*)d_out;

    proj_kernel<<<NT/32, 512>>>(x, Wq_d, bq_d, W_qk, b_qk, Wkv_d, bkv_d);
    precM_kernel<<<dim3(DM/256, NH), 256>>>(Wv_u, Wo, bv_u);
    biascomb_kernel<<<DM/256, 256>>>(bo);
    attn_kernel<<<dim3(SS/256, NH, BB), 256>>>();
    final_kernel<<<dim3(DM/64, NT/128), 256>>>(out);
}